// round 11
// baseline (speedup 1.0000x reference)
#include <cuda_runtime.h>

#define B_   8
#define LQ   5376
#define NQ   (B_*LQ)   // 43008

// Scratch buffers (no cudaMalloc allowed)
__device__ float g_value[(size_t)NQ * 128];   // (B,Lq,16,8)
__device__ float g_offs [(size_t)NQ * 384];   // (B,Lq,16,3,4,2)
__device__ float g_attn [(size_t)NQ * 192];   // (B,Lq,16,12) raw logits
__device__ float g_sampled[(size_t)NQ * 128]; // (B,Lq,16,8) after sampling

// Packed fp32x2 FMA (double-rate fp32, exact fp32 semantics)
__device__ __forceinline__ unsigned long long fma2(unsigned long long a,
                                                   unsigned long long b,
                                                   unsigned long long c) {
    unsigned long long d;
    asm("fma.rn.f32x2 %0, %1, %2, %3;" : "=l"(d) : "l"(a), "l"(b), "l"(c));
    return d;
}
__device__ __forceinline__ float2 unpack2(unsigned long long u) {
    float2 f;
    asm("mov.b64 {%0, %1}, %2;" : "=f"(f.x), "=f"(f.y) : "l"(u));
    return f;
}

// ---------------------------------------------------------------------------
// Kernel 1: fused projection GEMM  x[NQ,128] @ [W_val | W_off | W_attn] + bias
// Tile 128 queries x 64 cols, K chunked by 32.
// fp32x2 inner loop: A row-pairs read directly as u64 from normal [k][r]
// layout (a float4 = two (r,r+1) pairs); W splatted (w,w) in smem.
// Per k per thread: 4x LDS.128 + 16 fma2 (= 32 FMA), fma-pipe cycles halved.
// 128-query tiles never straddle level/batch boundaries.
// ---------------------------------------------------------------------------
__global__ __launch_bounds__(256) void proj_kernel(
    const float* __restrict__ fm0, const float* __restrict__ fm1, const float* __restrict__ fm2,
    const float* __restrict__ Wv, const float* __restrict__ bv,
    const float* __restrict__ Wo, const float* __restrict__ bo,
    const float* __restrict__ Wa, const float* __restrict__ ba)
{
    __shared__ float  As[32][128];   // [k][r]            16 KB
    __shared__ float2 W2[32][64];    // [k][c] splatted   16 KB

    const int tid = threadIdx.x;
    const int qg0 = blockIdx.x * 128;
    const int n0  = blockIdx.y * 64;

    // ---- A gather mapping: r = query within tile ----
    const int rA  = tid & 127;       // 0..127
    const int kbA = tid >> 7;        // 0..1
    const int qg = qg0 + rA;
    const int b  = qg / LQ;
    const int q  = qg - b * LQ;
    const float* fmp; int HW, pos;
    if (q < 4096)      { fmp = fm0; HW = 4096; pos = q; }
    else if (q < 5120) { fmp = fm1; HW = 1024; pos = q - 4096; }
    else               { fmp = fm2; HW = 256;  pos = q - 5120; }
    const float* xbase = fmp + (size_t)b * 128 * HW + pos;

    // ---- W mapping: this block's 64 columns lie in exactly one matrix ----
    const float* Wm; const float* bm; int wstride; int nloc0;
    if (n0 < 128)      { Wm = Wv; bm = bv; wstride = 128; nloc0 = n0; }
    else if (n0 < 512) { Wm = Wo; bm = bo; wstride = 384; nloc0 = n0 - 128; }
    else               { Wm = Wa; bm = ba; wstride = 192; nloc0 = n0 - 512; }

    const int cW  = tid & 63;        // 0..63
    const int kbW = tid >> 6;        // 0..3

    // ---- micro-tile mapping: 8 rows (4 row-pairs) x 4 cols per thread ----
    const int tx = tid & 15, ty = tid >> 4;   // 16 x 16
    const int r0 = ty * 8, c0 = tx * 4;

    // acc[rp][c]: row pair (r0+2rp, r0+2rp+1), col c0+c
    unsigned long long acc[4][4];
    #pragma unroll
    for (int i = 0; i < 4; i++)
        #pragma unroll
        for (int j = 0; j < 4; j++) acc[i][j] = 0ull;

    for (int kk = 0; kk < 128; kk += 32) {
        // load A chunk: 32x128, 16 elems/thread, coalesced over r
        #pragma unroll
        for (int i = 0; i < 16; i++) {
            int k = kbA + i * 2;                      // 0..31
            As[k][rA] = xbase[(size_t)(kk + k) * HW];
        }
        // load W chunk: 32x64, 8 elems/thread, splat-stored
        #pragma unroll
        for (int i = 0; i < 8; i++) {
            int k = kbW + i * 4;
            float w = Wm[(size_t)(kk + k) * wstride + nloc0 + cW];
            W2[k][cW] = make_float2(w, w);
        }
        __syncthreads();
        #pragma unroll
        for (int k = 0; k < 32; k++) {
            // A row-pairs: a01.x=(r0,r0+1) a01.y=(r0+2,r0+3) etc.
            ulonglong2 a01 = *(const ulonglong2*)&As[k][r0];
            ulonglong2 a23 = *(const ulonglong2*)&As[k][r0 + 4];
            // W splats: w01.x=(wc0,wc0) w01.y=(wc1,wc1) etc.
            ulonglong2 w01 = *(const ulonglong2*)&W2[k][c0];
            ulonglong2 w23 = *(const ulonglong2*)&W2[k][c0 + 2];
            acc[0][0] = fma2(a01.x, w01.x, acc[0][0]);
            acc[0][1] = fma2(a01.x, w01.y, acc[0][1]);
            acc[0][2] = fma2(a01.x, w23.x, acc[0][2]);
            acc[0][3] = fma2(a01.x, w23.y, acc[0][3]);
            acc[1][0] = fma2(a01.y, w01.x, acc[1][0]);
            acc[1][1] = fma2(a01.y, w01.y, acc[1][1]);
            acc[1][2] = fma2(a01.y, w23.x, acc[1][2]);
            acc[1][3] = fma2(a01.y, w23.y, acc[1][3]);
            acc[2][0] = fma2(a23.x, w01.x, acc[2][0]);
            acc[2][1] = fma2(a23.x, w01.y, acc[2][1]);
            acc[2][2] = fma2(a23.x, w23.x, acc[2][2]);
            acc[2][3] = fma2(a23.x, w23.y, acc[2][3]);
            acc[3][0] = fma2(a23.y, w01.x, acc[3][0]);
            acc[3][1] = fma2(a23.y, w01.y, acc[3][1]);
            acc[3][2] = fma2(a23.y, w23.x, acc[3][2]);
            acc[3][3] = fma2(a23.y, w23.y, acc[3][3]);
        }
        __syncthreads();
    }

    // Epilogue: add bias, scatter to the right scratch buffer
    float bias[4];
    #pragma unroll
    for (int j = 0; j < 4; j++) bias[j] = bm[nloc0 + c0 + j];

    #pragma unroll
    for (int rp = 0; rp < 4; rp++) {
        size_t qe = (size_t)(qg0 + r0 + 2 * rp);      // even row
        size_t qo = qe + 1;                           // odd row
        float ve[4], vo[4];
        #pragma unroll
        for (int j = 0; j < 4; j++) {
            float2 p = unpack2(acc[rp][j]);
            ve[j] = p.x + bias[j];
            vo[j] = p.y + bias[j];
        }
        #pragma unroll
        for (int j = 0; j < 4; j++) {
            int n = n0 + c0 + j;
            if (n0 < 128) {
                g_value[qe * 128 + n] = ve[j];
                g_value[qo * 128 + n] = vo[j];
            } else if (n0 < 512) {
                g_offs[qe * 384 + (n - 128)] = ve[j];
                g_offs[qo * 384 + (n - 128)] = vo[j];
            } else {
                g_attn[qe * 192 + (n - 512)] = ve[j];
                g_attn[qo * 192 + (n - 512)] = vo[j];
            }
        }
    }
}

// ---------------------------------------------------------------------------
// Kernel 2: per-query softmax + bilinear sampling.
// 4 queries per 256-thread block arranged as a 2x2 SPATIAL PATCH (same level)
// so the 4 queries' bilinear footprints overlap -> L1 captures reuse.
// Per query 64 threads = 16 heads x 4 channel-pairs (float2 gathers).
// ---------------------------------------------------------------------------
__global__ __launch_bounds__(256) void sample_kernel()
{
    const int t   = threadIdx.x;
    const int qi  = t >> 6;          // 0..3 patch slot: (qi&1)=dx, (qi>>1)=dy
    const int lt  = t & 63;
    const int h   = lt >> 2;         // 0..15
    const int chp = lt & 3;          // channel pair 0..3

    // block -> (batch, level, 2x2 patch)
    const int blk = blockIdx.x;                  // 0 .. NQ/4-1
    const int b   = blk / 1344;                  // 1344 patches per batch
    const int j   = blk - b * 1344;
    int Wq, qbase, p, shift;
    if (j < 1024)      { p = j;        Wq = 64; qbase = 0;    shift = 5; }
    else if (j < 1280) { p = j - 1024; Wq = 32; qbase = 4096; shift = 4; }
    else               { p = j - 1280; Wq = 16; qbase = 5120; shift = 3; }
    const int py = p >> shift;                   // patch row (pw = Wq/2)
    const int px = p - (py << shift);            // patch col
    const int posq = ((py << 1) + (qi >> 1)) * Wq + (px << 1) + (qi & 1);
    const int q  = qbase + posq;
    const int qg = b * LQ + q;

    const float invWq = 1.f / (float)Wq;
    const float refx = ((posq % Wq) + 0.5f) * invWq;
    const float refy = ((posq / Wq) + 0.5f) * invWq;

    __shared__ float s_attn[4][192];
    __shared__ float s_offs[4][384];
    {
        const size_t abase = (size_t)qg * 192;
        const size_t obase = (size_t)qg * 384;
        #pragma unroll
        for (int i = 0; i < 3; i++) s_attn[qi][lt + i * 64] = g_attn[abase + lt + i * 64];
        #pragma unroll
        for (int i = 0; i < 6; i++) s_offs[qi][lt + i * 64] = g_offs[obase + lt + i * 64];
    }
    __syncthreads();

    // Softmax over the 12 (level,point) logits of this head
    float av[12];
    float m = -1e30f;
    #pragma unroll
    for (int pp = 0; pp < 12; pp++) { av[pp] = s_attn[qi][h * 12 + pp]; m = fmaxf(m, av[pp]); }
    float s = 0.f;
    #pragma unroll
    for (int pp = 0; pp < 12; pp++) { av[pp] = __expf(av[pp] - m); s += av[pp]; }
    const float inv = 1.f / s;

    const int Ws_[3] = {64, 32, 16};
    const int st [3] = {0, 4096, 5120};

    float2 acc = make_float2(0.f, 0.f);
    #pragma unroll
    for (int l = 0; l < 3; l++) {
        const int   Wl = Ws_[l];
        const float fW = (float)Wl;
        const float* vbase = g_value + ((size_t)(b * LQ + st[l])) * 128 + h * 8 + chp * 2;
        #pragma unroll
        for (int pp = 0; pp < 4; pp++) {
            float ox = s_offs[qi][h * 24 + (l * 4 + pp) * 2 + 0];
            float oy = s_offs[qi][h * 24 + (l * 4 + pp) * 2 + 1];
            float x = (refx + ox / fW) * fW - 0.5f;
            float y = (refy + oy / fW) * fW - 0.5f;
            float x0f = floorf(x), y0f = floorf(y);
            int   x0 = (int)x0f,  y0 = (int)y0f;
            float wx1 = x - x0f, wx0 = 1.f - wx1;
            float wy1 = y - y0f, wy0 = 1.f - wy1;
            float aw = av[l * 4 + pp] * inv;
            #pragma unroll
            for (int dy = 0; dy < 2; dy++) {
                int yi = y0 + dy;
                if ((unsigned)yi >= (unsigned)Wl) continue;
                float wy = dy ? wy1 : wy0;
                #pragma unroll
                for (int dx = 0; dx < 2; dx++) {
                    int xi = x0 + dx;
                    if ((unsigned)xi >= (unsigned)Wl) continue;
                    float wx = dx ? wx1 : wx0;
                    float w = aw * wy * wx;
                    float2 v = *(const float2*)&vbase[(size_t)(yi * Wl + xi) * 128];
                    acc.x += w * v.x;
                    acc.y += w * v.y;
                }
            }
        }
    }
    *(float2*)&g_sampled[(size_t)qg * 128 + h * 8 + chp * 2] = acc;
}

// ---------------------------------------------------------------------------
// Kernel 3: output projection  sampled[NQ,128] @ W_out[128,128] + b_out,
// scattered into (B,128,H,W) per-level layout via smem transpose.
// ---------------------------------------------------------------------------
__global__ __launch_bounds__(256) void out_kernel(
    const float* __restrict__ Wout, const float* __restrict__ bout,
    float* __restrict__ out)
{
    __shared__ float As[64][65];   // [r][k]  (+1 pad)
    __shared__ float Ws[64][64];   // [k][c]
    __shared__ float Os[64][65];   // [r][c]  (+1 pad)

    const int tid = threadIdx.x;
    const int qg0 = blockIdx.x * 64;
    const int n0  = blockIdx.y * 64;
    const int tx = tid & 15, ty = tid >> 4;
    const int r0 = ty * 4, c0 = tx * 4;

    float acc[4][4];
    #pragma unroll
    for (int i = 0; i < 4; i++)
        #pragma unroll
        for (int j = 0; j < 4; j++) acc[i][j] = 0.f;

    const int kl = tid & 63;
    const int rb = tid >> 6;

    for (int kk = 0; kk < 128; kk += 64) {
        #pragma unroll
        for (int i = 0; i < 16; i++) {
            int r_ = rb + 4 * i;
            As[r_][kl] = g_sampled[(size_t)(qg0 + r_) * 128 + kk + kl];
        }
        #pragma unroll
        for (int i = 0; i < 16; i++) {
            int k_ = rb + 4 * i;
            Ws[k_][kl] = Wout[(size_t)(kk + k_) * 128 + n0 + kl];
        }
        __syncthreads();
        #pragma unroll
        for (int k = 0; k < 64; k++) {
            float4 w = *(const float4*)&Ws[k][c0];
            float a0 = As[r0 + 0][k], a1 = As[r0 + 1][k];
            float a2 = As[r0 + 2][k], a3 = As[r0 + 3][k];
            acc[0][0] += a0 * w.x; acc[0][1] += a0 * w.y; acc[0][2] += a0 * w.z; acc[0][3] += a0 * w.w;
            acc[1][0] += a1 * w.x; acc[1][1] += a1 * w.y; acc[1][2] += a1 * w.z; acc[1][3] += a1 * w.w;
            acc[2][0] += a2 * w.x; acc[2][1] += a2 * w.y; acc[2][2] += a2 * w.z; acc[2][3] += a2 * w.w;
            acc[3][0] += a3 * w.x; acc[3][1] += a3 * w.y; acc[3][2] += a3 * w.z; acc[3][3] += a3 * w.w;
        }
        __syncthreads();
    }

    #pragma unroll
    for (int i = 0; i < 4; i++)
        #pragma unroll
        for (int j = 0; j < 4; j++)
            Os[r0 + i][c0 + j] = acc[i][j] + bout[n0 + c0 + j];
    __syncthreads();

    // Coalesced scatter: consecutive threads -> consecutive queries (pos)
    for (int cc = 0; cc < 64; cc += 4) {
        int c = cc + (tid >> 6);
        int r = tid & 63;
        int qg = qg0 + r;
        int b = qg / LQ;
        int q = qg - b * LQ;
        int n = n0 + c;
        size_t addr;
        if (q < 4096)      addr = ((size_t)(b * 128 + n)) * 4096 + q;
        else if (q < 5120) addr = 4194304u + ((size_t)(b * 128 + n)) * 1024 + (q - 4096);
        else               addr = 5242880u + ((size_t)(b * 128 + n)) * 256  + (q - 5120);
        out[addr] = Os[r][c];
    }
}

extern "C" void kernel_launch(void* const* d_in, const int* in_sizes, int n_in,
                              void* d_out, int out_size)
{
    const float* fm0   = (const float*)d_in[0];
    const float* fm1   = (const float*)d_in[1];
    const float* fm2   = (const float*)d_in[2];
    const float* W_off = (const float*)d_in[3];
    const float* b_off = (const float*)d_in[4];
    const float* W_att = (const float*)d_in[5];
    const float* b_att = (const float*)d_in[6];
    const float* W_val = (const float*)d_in[7];
    const float* b_val = (const float*)d_in[8];
    const float* W_out = (const float*)d_in[9];
    const float* b_out = (const float*)d_in[10];
    float* out = (float*)d_out;

    dim3 g1(NQ / 128, 11);
    proj_kernel<<<g1, 256>>>(fm0, fm1, fm2, W_val, b_val, W_off, b_off, W_att, b_att);

    sample_kernel<<<NQ / 4, 256>>>();

    dim3 g3(NQ / 64, 2);
    out_kernel<<<g3, 256>>>(W_out, b_out, out);
}

// round 12
// speedup vs baseline: 2.1637x; 2.1637x over previous
#include <cuda_runtime.h>

#define B_   8
#define LQ   5376
#define NQ   (B_*LQ)   // 43008

// Scratch buffers (no cudaMalloc allowed)
// g_value is HEAD-MAJOR: [h][qg][8ch]  (texel = 32B = one L2 sector;
// x-adjacent texels contiguous -> bilinear/query locality lands in L1)
__device__ float g_value[(size_t)16 * NQ * 8];
__device__ float g_offs [(size_t)NQ * 384];   // (B,Lq,16,3,4,2)
__device__ float g_attn [(size_t)NQ * 192];   // (B,Lq,16,12) raw logits
__device__ float g_sampled[(size_t)NQ * 128]; // (B,Lq,16,8) after sampling

// ---------------------------------------------------------------------------
// Kernel 1: fused projection GEMM  x[NQ,128] @ [W_val | W_off | W_attn] + bias
// x gathered on the fly from the 3 feature maps.
// Tile 128 queries x 64 cols, K chunked by 32, 8x4 per-thread micro-tile:
// per k per thread = 3x LDS.128 + 32 FFMA (A loads are warp-broadcast).
// Value block scattered head-major. 128-query tiles never straddle
// level/batch boundaries.
// ---------------------------------------------------------------------------
__global__ __launch_bounds__(256) void proj_kernel(
    const float* __restrict__ fm0, const float* __restrict__ fm1, const float* __restrict__ fm2,
    const float* __restrict__ Wv, const float* __restrict__ bv,
    const float* __restrict__ Wo, const float* __restrict__ bo,
    const float* __restrict__ Wa, const float* __restrict__ ba)
{
    __shared__ float As[32][128];   // [k][r]  16 KB
    __shared__ float Ws[32][64];    // [k][c]   8 KB

    const int tid = threadIdx.x;
    const int qg0 = blockIdx.x * 128;
    const int n0  = blockIdx.y * 64;

    // ---- A gather mapping: r = query within tile ----
    const int rA  = tid & 127;       // 0..127
    const int kbA = tid >> 7;        // 0..1
    const int qg = qg0 + rA;
    const int b  = qg / LQ;
    const int q  = qg - b * LQ;
    const float* fmp; int HW, pos;
    if (q < 4096)      { fmp = fm0; HW = 4096; pos = q; }
    else if (q < 5120) { fmp = fm1; HW = 1024; pos = q - 4096; }
    else               { fmp = fm2; HW = 256;  pos = q - 5120; }
    const float* xbase = fmp + (size_t)b * 128 * HW + pos;

    // ---- W mapping: this block's 64 columns lie in exactly one matrix ----
    const float* Wm; const float* bm; int wstride; int nloc0;
    if (n0 < 128)      { Wm = Wv; bm = bv; wstride = 128; nloc0 = n0; }
    else if (n0 < 512) { Wm = Wo; bm = bo; wstride = 384; nloc0 = n0 - 128; }
    else               { Wm = Wa; bm = ba; wstride = 192; nloc0 = n0 - 512; }

    const int cW  = tid & 63;        // 0..63
    const int kbW = tid >> 6;        // 0..3

    // ---- micro-tile mapping ----
    const int tx = tid & 15, ty = tid >> 4;   // 16 x 16
    const int r0 = ty * 8, c0 = tx * 4;

    float acc[8][4];
    #pragma unroll
    for (int i = 0; i < 8; i++)
        #pragma unroll
        for (int j = 0; j < 4; j++) acc[i][j] = 0.f;

    for (int kk = 0; kk < 128; kk += 32) {
        // load A chunk: 32x128, 16 elems/thread, coalesced over r
        #pragma unroll
        for (int i = 0; i < 16; i++) {
            int k = kbA + i * 2;                      // 0..31
            As[k][rA] = xbase[(size_t)(kk + k) * HW];
        }
        // load W chunk: 32x64, 8 elems/thread, coalesced over c
        #pragma unroll
        for (int i = 0; i < 8; i++) {
            int k = kbW + i * 4;
            Ws[k][cW] = Wm[(size_t)(kk + k) * wstride + nloc0 + cW];
        }
        __syncthreads();
        #pragma unroll
        for (int k = 0; k < 32; k++) {
            float4 a0 = *(const float4*)&As[k][r0];
            float4 a1 = *(const float4*)&As[k][r0 + 4];
            float4 w  = *(const float4*)&Ws[k][c0];
            acc[0][0] += a0.x * w.x; acc[0][1] += a0.x * w.y; acc[0][2] += a0.x * w.z; acc[0][3] += a0.x * w.w;
            acc[1][0] += a0.y * w.x; acc[1][1] += a0.y * w.y; acc[1][2] += a0.y * w.z; acc[1][3] += a0.y * w.w;
            acc[2][0] += a0.z * w.x; acc[2][1] += a0.z * w.y; acc[2][2] += a0.z * w.z; acc[2][3] += a0.z * w.w;
            acc[3][0] += a0.w * w.x; acc[3][1] += a0.w * w.y; acc[3][2] += a0.w * w.z; acc[3][3] += a0.w * w.w;
            acc[4][0] += a1.x * w.x; acc[4][1] += a1.x * w.y; acc[4][2] += a1.x * w.z; acc[4][3] += a1.x * w.w;
            acc[5][0] += a1.y * w.x; acc[5][1] += a1.y * w.y; acc[5][2] += a1.y * w.z; acc[5][3] += a1.y * w.w;
            acc[6][0] += a1.z * w.x; acc[6][1] += a1.z * w.y; acc[6][2] += a1.z * w.z; acc[6][3] += a1.z * w.w;
            acc[7][0] += a1.w * w.x; acc[7][1] += a1.w * w.y; acc[7][2] += a1.w * w.z; acc[7][3] += a1.w * w.w;
        }
        __syncthreads();
    }

    // Epilogue: add bias, scatter
    float bias[4];
    #pragma unroll
    for (int j = 0; j < 4; j++) bias[j] = bm[nloc0 + c0 + j];

    if (n0 < 128) {
        // head-major value store: float4 chunk at [h0][qg][ch0..ch0+3]
        const int h0  = (n0 + c0) >> 3;     // c0 multiple of 4
        const int ch0 = (n0 + c0) & 7;      // 0 or 4
        #pragma unroll
        for (int i = 0; i < 8; i++) {
            size_t qg_w = (size_t)(qg0 + r0 + i);
            float4 v = make_float4(acc[i][0] + bias[0], acc[i][1] + bias[1],
                                   acc[i][2] + bias[2], acc[i][3] + bias[3]);
            *(float4*)&g_value[((size_t)h0 * NQ + qg_w) * 8 + ch0] = v;
        }
    } else if (n0 < 512) {
        #pragma unroll
        for (int i = 0; i < 8; i++) {
            size_t qg_w = (size_t)(qg0 + r0 + i);
            #pragma unroll
            for (int j = 0; j < 4; j++)
                g_offs[qg_w * 384 + (n0 - 128) + c0 + j] = acc[i][j] + bias[j];
        }
    } else {
        #pragma unroll
        for (int i = 0; i < 8; i++) {
            size_t qg_w = (size_t)(qg0 + r0 + i);
            #pragma unroll
            for (int j = 0; j < 4; j++)
                g_attn[qg_w * 192 + (n0 - 512) + c0 + j] = acc[i][j] + bias[j];
        }
    }
}

// ---------------------------------------------------------------------------
// Kernel 2: per-query softmax + bilinear sampling.
// 4 consecutive queries per 256-thread block; per query 64 threads =
// 16 heads x 4 channel-pairs (float2 gathers from head-major value).
// ---------------------------------------------------------------------------
__global__ __launch_bounds__(256) void sample_kernel()
{
    const int t   = threadIdx.x;
    const int qi  = t >> 6;          // 0..3 query slot
    const int lt  = t & 63;
    const int h   = lt >> 2;         // 0..15
    const int chp = lt & 3;          // channel pair 0..3

    const int qg = blockIdx.x * 4 + qi;
    const int b = qg / LQ;
    const int q = qg - b * LQ;
    int posq, Wq;
    if (q < 4096)      { posq = q;        Wq = 64; }
    else if (q < 5120) { posq = q - 4096; Wq = 32; }
    else               { posq = q - 5120; Wq = 16; }
    const float invWq = 1.f / (float)Wq;
    const float refx = ((posq % Wq) + 0.5f) * invWq;
    const float refy = ((posq / Wq) + 0.5f) * invWq;

    __shared__ float s_attn[4][192];
    __shared__ float s_offs[4][384];
    {
        const size_t abase = (size_t)qg * 192;
        const size_t obase = (size_t)qg * 384;
        #pragma unroll
        for (int i = 0; i < 3; i++) s_attn[qi][lt + i * 64] = g_attn[abase + lt + i * 64];
        #pragma unroll
        for (int i = 0; i < 6; i++) s_offs[qi][lt + i * 64] = g_offs[obase + lt + i * 64];
    }
    __syncthreads();

    // Softmax over the 12 (level,point) logits of this head
    float av[12];
    float m = -1e30f;
    #pragma unroll
    for (int p = 0; p < 12; p++) { av[p] = s_attn[qi][h * 12 + p]; m = fmaxf(m, av[p]); }
    float s = 0.f;
    #pragma unroll
    for (int p = 0; p < 12; p++) { av[p] = __expf(av[p] - m); s += av[p]; }
    const float inv = 1.f / s;

    const int Ws_[3] = {64, 32, 16};
    const int st [3] = {0, 4096, 5120};

    float2 acc = make_float2(0.f, 0.f);
    #pragma unroll
    for (int l = 0; l < 3; l++) {
        const int   Wl = Ws_[l];
        const float fW = (float)Wl;
        // head-major: texel stride = 8 floats (32B)
        const float* vbase = g_value + ((size_t)h * NQ + b * LQ + st[l]) * 8 + chp * 2;
        #pragma unroll
        for (int p = 0; p < 4; p++) {
            float ox = s_offs[qi][h * 24 + (l * 4 + p) * 2 + 0];
            float oy = s_offs[qi][h * 24 + (l * 4 + p) * 2 + 1];
            float x = (refx + ox / fW) * fW - 0.5f;
            float y = (refy + oy / fW) * fW - 0.5f;
            float x0f = floorf(x), y0f = floorf(y);
            int   x0 = (int)x0f,  y0 = (int)y0f;
            float wx1 = x - x0f, wx0 = 1.f - wx1;
            float wy1 = y - y0f, wy0 = 1.f - wy1;
            float aw = av[l * 4 + p] * inv;
            #pragma unroll
            for (int dy = 0; dy < 2; dy++) {
                int yi = y0 + dy;
                if ((unsigned)yi >= (unsigned)Wl) continue;
                float wy = dy ? wy1 : wy0;
                #pragma unroll
                for (int dx = 0; dx < 2; dx++) {
                    int xi = x0 + dx;
                    if ((unsigned)xi >= (unsigned)Wl) continue;
                    float wx = dx ? wx1 : wx0;
                    float w = aw * wy * wx;
                    float2 v = *(const float2*)&vbase[(size_t)(yi * Wl + xi) * 8];
                    acc.x += w * v.x;
                    acc.y += w * v.y;
                }
            }
        }
    }
    *(float2*)&g_sampled[(size_t)qg * 128 + h * 8 + chp * 2] = acc;
}

// ---------------------------------------------------------------------------
// Kernel 3: output projection  sampled[NQ,128] @ W_out[128,128] + b_out,
// scattered into (B,128,H,W) per-level layout via smem transpose.
// ---------------------------------------------------------------------------
__global__ __launch_bounds__(256) void out_kernel(
    const float* __restrict__ Wout, const float* __restrict__ bout,
    float* __restrict__ out)
{
    __shared__ float As[64][65];   // [r][k]  (+1 pad)
    __shared__ float Ws[64][64];   // [k][c]
    __shared__ float Os[64][65];   // [r][c]  (+1 pad)

    const int tid = threadIdx.x;
    const int qg0 = blockIdx.x * 64;
    const int n0  = blockIdx.y * 64;
    const int tx = tid & 15, ty = tid >> 4;
    const int r0 = ty * 4, c0 = tx * 4;

    float acc[4][4];
    #pragma unroll
    for (int i = 0; i < 4; i++)
        #pragma unroll
        for (int j = 0; j < 4; j++) acc[i][j] = 0.f;

    const int kl = tid & 63;
    const int rb = tid >> 6;

    for (int kk = 0; kk < 128; kk += 64) {
        #pragma unroll
        for (int i = 0; i < 16; i++) {
            int r_ = rb + 4 * i;
            As[r_][kl] = g_sampled[(size_t)(qg0 + r_) * 128 + kk + kl];
        }
        #pragma unroll
        for (int i = 0; i < 16; i++) {
            int k_ = rb + 4 * i;
            Ws[k_][kl] = Wout[(size_t)(kk + k_) * 128 + n0 + kl];
        }
        __syncthreads();
        #pragma unroll
        for (int k = 0; k < 64; k++) {
            float4 w = *(const float4*)&Ws[k][c0];
            float a0 = As[r0 + 0][k], a1 = As[r0 + 1][k];
            float a2 = As[r0 + 2][k], a3 = As[r0 + 3][k];
            acc[0][0] += a0 * w.x; acc[0][1] += a0 * w.y; acc[0][2] += a0 * w.z; acc[0][3] += a0 * w.w;
            acc[1][0] += a1 * w.x; acc[1][1] += a1 * w.y; acc[1][2] += a1 * w.z; acc[1][3] += a1 * w.w;
            acc[2][0] += a2 * w.x; acc[2][1] += a2 * w.y; acc[2][2] += a2 * w.z; acc[2][3] += a2 * w.w;
            acc[3][0] += a3 * w.x; acc[3][1] += a3 * w.y; acc[3][2] += a3 * w.z; acc[3][3] += a3 * w.w;
        }
        __syncthreads();
    }

    #pragma unroll
    for (int i = 0; i < 4; i++)
        #pragma unroll
        for (int j = 0; j < 4; j++)
            Os[r0 + i][c0 + j] = acc[i][j] + bout[n0 + c0 + j];
    __syncthreads();

    // Coalesced scatter: consecutive threads -> consecutive queries (pos)
    for (int cc = 0; cc < 64; cc += 4) {
        int c = cc + (tid >> 6);
        int r = tid & 63;
        int qg = qg0 + r;
        int b = qg / LQ;
        int q = qg - b * LQ;
        int n = n0 + c;
        size_t addr;
        if (q < 4096)      addr = ((size_t)(b * 128 + n)) * 4096 + q;
        else if (q < 5120) addr = 4194304u + ((size_t)(b * 128 + n)) * 1024 + (q - 4096);
        else               addr = 5242880u + ((size_t)(b * 128 + n)) * 256  + (q - 5120);
        out[addr] = Os[r][c];
    }
}

extern "C" void kernel_launch(void* const* d_in, const int* in_sizes, int n_in,
                              void* d_out, int out_size)
{
    const float* fm0   = (const float*)d_in[0];
    const float* fm1   = (const float*)d_in[1];
    const float* fm2   = (const float*)d_in[2];
    const float* W_off = (const float*)d_in[3];
    const float* b_off = (const float*)d_in[4];
    const float* W_att = (const float*)d_in[5];
    const float* b_att = (const float*)d_in[6];
    const float* W_val = (const float*)d_in[7];
    const float* b_val = (const float*)d_in[8];
    const float* W_out = (const float*)d_in[9];
    const float* b_out = (const float*)d_in[10];
    float* out = (float*)d_out;

    dim3 g1(NQ / 128, 11);
    proj_kernel<<<g1, 256>>>(fm0, fm1, fm2, W_val, b_val, W_off, b_off, W_att, b_att);

    sample_kernel<<<NQ / 4, 256>>>();

    dim3 g3(NQ / 64, 2);
    out_kernel<<<g3, 256>>>(W_out, b_out, out);
}

// round 13
// speedup vs baseline: 2.2515x; 1.0406x over previous
#include <cuda_runtime.h>
#include <cstdint>

#define B_   8
#define LQ   5376
#define NQ   (B_*LQ)   // 43008

// Scratch buffers (no cudaMalloc allowed)
__device__ float g_value[(size_t)NQ * 128];   // (B,Lq,16,8)
__device__ float g_offs [(size_t)NQ * 384];   // (B,Lq,16,3,4,2)
__device__ float g_attn [(size_t)NQ * 192];   // (B,Lq,16,12) raw logits
__device__ float g_sampled[(size_t)NQ * 128]; // (B,Lq,16,8) after sampling

// ---------------------------------------------------------------------------
// Kernel 1: fused projection GEMM  x[NQ,128] @ [W_val | W_off | W_attn] + bias
// Tile 128 queries x 64 cols, K chunked by 32, 8x4 per-thread micro-tile.
// cp.async double-buffered pipeline: chunk c+1 streams into the alternate
// smem buffer (16B LDGSTS, 6/thread/chunk) while chunk c computes.
// A vectorizes along q (contiguous pos run: 128q tiles never straddle
// level/batch boundaries); W along columns.
// ---------------------------------------------------------------------------
__global__ __launch_bounds__(256) void proj_kernel(
    const float* __restrict__ fm0, const float* __restrict__ fm1, const float* __restrict__ fm2,
    const float* __restrict__ Wv, const float* __restrict__ bv,
    const float* __restrict__ Wo, const float* __restrict__ bo,
    const float* __restrict__ Wa, const float* __restrict__ ba)
{
    __shared__ float As[2][32][128];   // [buf][k][r]  32 KB
    __shared__ float Ws[2][32][64];    // [buf][k][c]  16 KB

    const int tid = threadIdx.x;
    const int qg0 = blockIdx.x * 128;
    const int n0  = blockIdx.y * 64;

    // ---- level/batch resolved once per block (tile is one contiguous run) ----
    const int b  = qg0 / LQ;
    const int q0 = qg0 - b * LQ;
    const float* fmp; int HW, pos0;
    if (q0 < 4096)      { fmp = fm0; HW = 4096; pos0 = q0; }
    else if (q0 < 5120) { fmp = fm1; HW = 1024; pos0 = q0 - 4096; }
    else                { fmp = fm2; HW = 256;  pos0 = q0 - 5120; }
    const float* abase = fmp + (size_t)b * 128 * HW + pos0;

    // ---- W mapping: this block's 64 columns lie in exactly one matrix ----
    const float* Wm; const float* bm; int wstride; int nloc0;
    if (n0 < 128)      { Wm = Wv; bm = bv; wstride = 128; nloc0 = n0; }
    else if (n0 < 512) { Wm = Wo; bm = bo; wstride = 384; nloc0 = n0 - 128; }
    else               { Wm = Wa; bm = ba; wstride = 192; nloc0 = n0 - 512; }

    // ---- micro-tile mapping ----
    const int tx = tid & 15, ty = tid >> 4;   // 16 x 16
    const int r0 = ty * 8, c0 = tx * 4;

    float acc[8][4];
    #pragma unroll
    for (int i = 0; i < 8; i++)
        #pragma unroll
        for (int j = 0; j < 4; j++) acc[i][j] = 0.f;

    // ---- async chunk loader: 4x 16B for A, 2x 16B for W per thread ----
    auto load_chunk = [&](int kk, int buf) {
        #pragma unroll
        for (int j = 0; j < 4; j++) {
            int idx = j * 256 + tid;            // 0..1023
            int k   = idx >> 5;                 // 0..31
            int r4  = (idx & 31) << 2;          // 0,4,..,124
            uint32_t dst = (uint32_t)__cvta_generic_to_shared(&As[buf][k][r4]);
            const float* src = abase + (size_t)(kk + k) * HW + r4;
            asm volatile("cp.async.ca.shared.global [%0], [%1], 16;" :: "r"(dst), "l"(src));
        }
        #pragma unroll
        for (int j = 0; j < 2; j++) {
            int idx = j * 256 + tid;            // 0..511
            int k   = idx >> 4;                 // 0..31
            int c4  = (idx & 15) << 2;          // 0,4,..,60
            uint32_t dst = (uint32_t)__cvta_generic_to_shared(&Ws[buf][k][c4]);
            const float* src = Wm + (size_t)(kk + k) * wstride + nloc0 + c4;
            asm volatile("cp.async.ca.shared.global [%0], [%1], 16;" :: "r"(dst), "l"(src));
        }
        asm volatile("cp.async.commit_group;" ::: "memory");
    };

    load_chunk(0, 0);

    #pragma unroll
    for (int c = 0; c < 4; c++) {
        if (c < 3) {
            load_chunk((c + 1) * 32, (c + 1) & 1);
            asm volatile("cp.async.wait_group 1;" ::: "memory");
        } else {
            asm volatile("cp.async.wait_group 0;" ::: "memory");
        }
        __syncthreads();

        const int buf = c & 1;
        #pragma unroll
        for (int k = 0; k < 32; k++) {
            float4 a0 = *(const float4*)&As[buf][k][r0];
            float4 a1 = *(const float4*)&As[buf][k][r0 + 4];
            float4 w  = *(const float4*)&Ws[buf][k][c0];
            acc[0][0] += a0.x * w.x; acc[0][1] += a0.x * w.y; acc[0][2] += a0.x * w.z; acc[0][3] += a0.x * w.w;
            acc[1][0] += a0.y * w.x; acc[1][1] += a0.y * w.y; acc[1][2] += a0.y * w.z; acc[1][3] += a0.y * w.w;
            acc[2][0] += a0.z * w.x; acc[2][1] += a0.z * w.y; acc[2][2] += a0.z * w.z; acc[2][3] += a0.z * w.w;
            acc[3][0] += a0.w * w.x; acc[3][1] += a0.w * w.y; acc[3][2] += a0.w * w.z; acc[3][3] += a0.w * w.w;
            acc[4][0] += a1.x * w.x; acc[4][1] += a1.x * w.y; acc[4][2] += a1.x * w.z; acc[4][3] += a1.x * w.w;
            acc[5][0] += a1.y * w.x; acc[5][1] += a1.y * w.y; acc[5][2] += a1.y * w.z; acc[5][3] += a1.y * w.w;
            acc[6][0] += a1.z * w.x; acc[6][1] += a1.z * w.y; acc[6][2] += a1.z * w.z; acc[6][3] += a1.z * w.w;
            acc[7][0] += a1.w * w.x; acc[7][1] += a1.w * w.y; acc[7][2] += a1.w * w.z; acc[7][3] += a1.w * w.w;
        }
        __syncthreads();
    }

    // Epilogue: add bias, scatter to the right scratch buffer (q-major)
    float bias[4];
    #pragma unroll
    for (int j = 0; j < 4; j++) bias[j] = bm[nloc0 + c0 + j];

    if (n0 < 128) {
        #pragma unroll
        for (int i = 0; i < 8; i++) {
            size_t qg_w = (size_t)(qg0 + r0 + i);
            float4 v = make_float4(acc[i][0] + bias[0], acc[i][1] + bias[1],
                                   acc[i][2] + bias[2], acc[i][3] + bias[3]);
            *(float4*)&g_value[qg_w * 128 + n0 + c0] = v;
        }
    } else if (n0 < 512) {
        #pragma unroll
        for (int i = 0; i < 8; i++) {
            size_t qg_w = (size_t)(qg0 + r0 + i);
            #pragma unroll
            for (int j = 0; j < 4; j++)
                g_offs[qg_w * 384 + (n0 - 128) + c0 + j] = acc[i][j] + bias[j];
        }
    } else {
        #pragma unroll
        for (int i = 0; i < 8; i++) {
            size_t qg_w = (size_t)(qg0 + r0 + i);
            #pragma unroll
            for (int j = 0; j < 4; j++)
                g_attn[qg_w * 192 + (n0 - 512) + c0 + j] = acc[i][j] + bias[j];
        }
    }
}

// ---------------------------------------------------------------------------
// Kernel 2: per-query softmax + bilinear sampling.
// 4 consecutive queries per 256-thread block; per query 64 threads =
// 16 heads x 4 channel-pairs (float2 gathers, q-major value).
// ---------------------------------------------------------------------------
__global__ __launch_bounds__(256) void sample_kernel()
{
    const int t   = threadIdx.x;
    const int qi  = t >> 6;          // 0..3 query slot
    const int lt  = t & 63;
    const int h   = lt >> 2;         // 0..15
    const int chp = lt & 3;          // channel pair 0..3

    const int qg = blockIdx.x * 4 + qi;
    const int b = qg / LQ;
    const int q = qg - b * LQ;
    int posq, Wq;
    if (q < 4096)      { posq = q;        Wq = 64; }
    else if (q < 5120) { posq = q - 4096; Wq = 32; }
    else               { posq = q - 5120; Wq = 16; }
    const float invWq = 1.f / (float)Wq;
    const float refx = ((posq % Wq) + 0.5f) * invWq;
    const float refy = ((posq / Wq) + 0.5f) * invWq;

    __shared__ float s_attn[4][192];
    __shared__ float s_offs[4][384];
    {
        const size_t abase = (size_t)qg * 192;
        const size_t obase = (size_t)qg * 384;
        #pragma unroll
        for (int i = 0; i < 3; i++) s_attn[qi][lt + i * 64] = g_attn[abase + lt + i * 64];
        #pragma unroll
        for (int i = 0; i < 6; i++) s_offs[qi][lt + i * 64] = g_offs[obase + lt + i * 64];
    }
    __syncthreads();

    // Softmax over the 12 (level,point) logits of this head
    float av[12];
    float m = -1e30f;
    #pragma unroll
    for (int p = 0; p < 12; p++) { av[p] = s_attn[qi][h * 12 + p]; m = fmaxf(m, av[p]); }
    float s = 0.f;
    #pragma unroll
    for (int p = 0; p < 12; p++) { av[p] = __expf(av[p] - m); s += av[p]; }
    const float inv = 1.f / s;

    const int Ws_[3] = {64, 32, 16};
    const int st [3] = {0, 4096, 5120};

    float2 acc = make_float2(0.f, 0.f);
    #pragma unroll
    for (int l = 0; l < 3; l++) {
        const int   Wl = Ws_[l];
        const float fW = (float)Wl;
        const float* vbase = g_value + ((size_t)(b * LQ + st[l])) * 128 + h * 8 + chp * 2;
        #pragma unroll
        for (int p = 0; p < 4; p++) {
            float ox = s_offs[qi][h * 24 + (l * 4 + p) * 2 + 0];
            float oy = s_offs[qi][h * 24 + (l * 4 + p) * 2 + 1];
            float x = (refx + ox / fW) * fW - 0.5f;
            float y = (refy + oy / fW) * fW - 0.5f;
            float x0f = floorf(x), y0f = floorf(y);
            int   x0 = (int)x0f,  y0 = (int)y0f;
            float wx1 = x - x0f, wx0 = 1.f - wx1;
            float wy1 = y - y0f, wy0 = 1.f - wy1;
            float aw = av[l * 4 + p] * inv;
            #pragma unroll
            for (int dy = 0; dy < 2; dy++) {
                int yi = y0 + dy;
                if ((unsigned)yi >= (unsigned)Wl) continue;
                float wy = dy ? wy1 : wy0;
                #pragma unroll
                for (int dx = 0; dx < 2; dx++) {
                    int xi = x0 + dx;
                    if ((unsigned)xi >= (unsigned)Wl) continue;
                    float wx = dx ? wx1 : wx0;
                    float w = aw * wy * wx;
                    float2 v = *(const float2*)&vbase[(size_t)(yi * Wl + xi) * 128];
                    acc.x += w * v.x;
                    acc.y += w * v.y;
                }
            }
        }
    }
    *(float2*)&g_sampled[(size_t)qg * 128 + h * 8 + chp * 2] = acc;
}

// ---------------------------------------------------------------------------
// Kernel 3: output projection  sampled[NQ,128] @ W_out[128,128] + b_out,
// scattered into (B,128,H,W) per-level layout via smem transpose.
// ---------------------------------------------------------------------------
__global__ __launch_bounds__(256) void out_kernel(
    const float* __restrict__ Wout, const float* __restrict__ bout,
    float* __restrict__ out)
{
    __shared__ float As[64][65];   // [r][k]  (+1 pad)
    __shared__ float Ws[64][64];   // [k][c]
    __shared__ float Os[64][65];   // [r][c]  (+1 pad)

    const int tid = threadIdx.x;
    const int qg0 = blockIdx.x * 64;
    const int n0  = blockIdx.y * 64;
    const int tx = tid & 15, ty = tid >> 4;
    const int r0 = ty * 4, c0 = tx * 4;

    float acc[4][4];
    #pragma unroll
    for (int i = 0; i < 4; i++)
        #pragma unroll
        for (int j = 0; j < 4; j++) acc[i][j] = 0.f;

    const int kl = tid & 63;
    const int rb = tid >> 6;

    for (int kk = 0; kk < 128; kk += 64) {
        #pragma unroll
        for (int i = 0; i < 16; i++) {
            int r_ = rb + 4 * i;
            As[r_][kl] = g_sampled[(size_t)(qg0 + r_) * 128 + kk + kl];
        }
        #pragma unroll
        for (int i = 0; i < 16; i++) {
            int k_ = rb + 4 * i;
            Ws[k_][kl] = Wout[(size_t)(kk + k_) * 128 + n0 + kl];
        }
        __syncthreads();
        #pragma unroll
        for (int k = 0; k < 64; k++) {
            float4 w = *(const float4*)&Ws[k][c0];
            float a0 = As[r0 + 0][k], a1 = As[r0 + 1][k];
            float a2 = As[r0 + 2][k], a3 = As[r0 + 3][k];
            acc[0][0] += a0 * w.x; acc[0][1] += a0 * w.y; acc[0][2] += a0 * w.z; acc[0][3] += a0 * w.w;
            acc[1][0] += a1 * w.x; acc[1][1] += a1 * w.y; acc[1][2] += a1 * w.z; acc[1][3] += a1 * w.w;
            acc[2][0] += a2 * w.x; acc[2][1] += a2 * w.y; acc[2][2] += a2 * w.z; acc[2][3] += a2 * w.w;
            acc[3][0] += a3 * w.x; acc[3][1] += a3 * w.y; acc[3][2] += a3 * w.z; acc[3][3] += a3 * w.w;
        }
        __syncthreads();
    }

    #pragma unroll
    for (int i = 0; i < 4; i++)
        #pragma unroll
        for (int j = 0; j < 4; j++)
            Os[r0 + i][c0 + j] = acc[i][j] + bout[n0 + c0 + j];
    __syncthreads();

    // Coalesced scatter: consecutive threads -> consecutive queries (pos)
    for (int cc = 0; cc < 64; cc += 4) {
        int c = cc + (tid >> 6);
        int r = tid & 63;
        int qg = qg0 + r;
        int b = qg / LQ;
        int q = qg - b * LQ;
        int n = n0 + c;
        size_t addr;
        if (q < 4096)      addr = ((size_t)(b * 128 + n)) * 4096 + q;
        else if (q < 5120) addr = 4194304u + ((size_t)(b * 128 + n)) * 1024 + (q - 4096);
        else               addr = 5242880u + ((size_t)(b * 128 + n)) * 256  + (q - 5120);
        out[addr] = Os[r][c];
    }
}

extern "C" void kernel_launch(void* const* d_in, const int* in_sizes, int n_in,
                              void* d_out, int out_size)
{
    const float* fm0   = (const float*)d_in[0];
    const float* fm1   = (const float*)d_in[1];
    const float* fm2   = (const float*)d_in[2];
    const float* W_off = (const float*)d_in[3];
    const float* b_off = (const float*)d_in[4];
    const float* W_att = (const float*)d_in[5];
    const float* b_att = (const float*)d_in[6];
    const float* W_val = (const float*)d_in[7];
    const float* b_val = (const float*)d_in[8];
    const float* W_out = (const float*)d_in[9];
    const float* b_out = (const float*)d_in[10];
    float* out = (float*)d_out;

    dim3 g1(NQ / 128, 11);
    proj_kernel<<<g1, 256>>>(fm0, fm1, fm2, W_val, b_val, W_off, b_off, W_att, b_att);

    sample_kernel<<<NQ / 4, 256>>>();

    dim3 g3(NQ / 64, 2);
    out_kernel<<<g3, 256>>>(W_out, b_out, out);
}